// round 12
// baseline (speedup 1.0000x reference)
#include <cuda_runtime.h>
#include <cstdint>

// TraceRNN: T=512, B=32, F=256, L=8
// out = [ final_trace : B*F*L ][ ys : T*B*F*L ]
// Fused chunked scan (16 chunks x 32 steps), quad-lambda threads, ONE kernel.
// R12: 128-thread blocks (QPB=8, grid=2048) for 64 warps/SM; snr back in smem;
//      packed f32x2 math kept.

#define TT  512
#define BB  32
#define FF  256
#define LL  8
#define BF  (BB * FF)        // 8192
#define BFL (BB * FF * LL)   // 65536
#define QQ  (BFL / 4)        // 16384 lambda-quads
#define CC  16
#define CL  32
#define QPB 8
#define NT  128
#define FSTR 516             // padded t-stride (words)
#define NPROD 16             // producer blocks

__device__ float g_snrT[BB * TT];   // [b][t] = reset ? 0 : 1
__device__ int   g_flag;            // monotonic producer counter

// ---- packed f32x2 helpers ----
#define PK2(d, lo, hi)  asm("mov.b64 %0, {%1,%2};" : "=l"(d) : "f"(lo), "f"(hi))
#define UPK2(lo, hi, s) asm("mov.b64 {%0,%1}, %2;" : "=f"(lo), "=f"(hi) : "l"(s))
#define MUL2(d, a, b)   asm("mul.rn.f32x2 %0, %1, %2;" : "=l"(d) : "l"(a), "l"(b))
#define SUB2(d, a, b)   asm("sub.rn.f32x2 %0, %1, %2;" : "=l"(d) : "l"(a), "l"(b))
#define FMA2(d, a, b, c) asm("fma.rn.f32x2 %0, %1, %2, %3;" : "=l"(d) : "l"(a), "l"(b), "l"(c))

__global__ __launch_bounds__(NT, 16) void trace_fused(
    const float* __restrict__ features,   // [T,B,F]
    const int*   __restrict__ resets,     // [T,B]
    const float* __restrict__ carry,      // [B,F,L]
    const float* __restrict__ lambdas,    // [L]
    float*       __restrict__ out)        // [BFL + T*BFL]
{
    __shared__ float  sfeatT[4 * FSTR];   // [fcol][t], ~8.3 KB
    __shared__ float  snr[TT];            // 2 KB
    __shared__ float4 sP[CC][QPB];        // 2 KB
    __shared__ float  spn[CC];

    const int tid  = threadIdx.x;
    const int ql   = tid & (QPB - 1);
    const int c    = tid >> 3;
    const int q    = blockIdx.x * QPB + ql;
    const int b    = q >> 9;
    const int col0 = blockIdx.x * 4;      // first feature col of block (4 cols)
    const int fcol = ql >> 1;             // 0..3
    const int t0   = c * CL;

    // ---- stage features transposed: one float4 per t ----
#pragma unroll
    for (int it = 0; it < 4; ++it) {
        const int t = it * NT + tid;      // 0..511
        float4 v = *(const float4*)(features + t * BF + col0);
        sfeatT[0 * FSTR + t] = v.x;
        sfeatT[1 * FSTR + t] = v.y;
        sfeatT[2 * FSTR + t] = v.z;
        sfeatT[3 * FSTR + t] = v.w;
    }

    // ---- producer blocks: transpose a 32-t slice of resets -> g_snrT ----
    if (blockIdx.x < NPROD) {
        const int tbase = blockIdx.x * 32;
#pragma unroll
        for (int it = 0; it < 8; ++it) {
            const int idx = it * NT + tid;        // 0..1023
            const int tl = idx >> 5, bb = idx & 31;
            g_snrT[bb * TT + tbase + tl] =
                (resets[(tbase + tl) * BB + bb] != 0) ? 0.0f : 1.0f;
        }
        __threadfence();
        __syncthreads();
        if (tid == 0) atomicAdd(&g_flag, 1);
    }

    const int   l0   = (q & 1) * 4;
    const float lam0 = __ldg(&lambdas[l0 + 0]);
    const float lam1 = __ldg(&lambdas[l0 + 1]);
    const float lam2 = __ldg(&lambdas[l0 + 2]);
    const float lam3 = __ldg(&lambdas[l0 + 3]);
    uint64_t lam01, lam23;
    PK2(lam01, lam0, lam1);
    PK2(lam23, lam2, lam3);

    // ---- wait for producers (launch-order-safe), then load snr ----
    if (tid == 0) {
        while (*(volatile int*)&g_flag < NPROD) { }
        __threadfence();
    }
    __syncthreads();

#pragma unroll
    for (int it = 0; it < 4; ++it)
        snr[it * NT + tid] = g_snrT[b * TT + it * NT + tid];

    __syncthreads();

    const float* fbase = sfeatT + fcol * FSTR + t0;

    // ---- Phase 1: chunk summary with zero init ----
    uint64_t t01 = 0ull, t23 = 0ull;
    float pn = 1.0f;

#define STEP(FV, NR)                                          \
    {   const float _f = (FV), _n = (NR);                     \
        uint64_t _nn, _ff, _a01, _a23, _d01, _d23;            \
        PK2(_nn, _n, _n);  PK2(_ff, _f, _f);                  \
        MUL2(_a01, lam01, _nn); MUL2(_a23, lam23, _nn);       \
        SUB2(_d01, t01, _ff);   SUB2(_d23, t23, _ff);         \
        FMA2(t01, _a01, _d01, _ff);                           \
        FMA2(t23, _a23, _d23, _ff);                           }

#pragma unroll
    for (int g = 0; g < CL / 4; ++g) {
        const float4 fv = *(const float4*)(fbase + 4 * g);
        const float4 nr = *(const float4*)(snr + t0 + 4 * g);
        pn = fminf(pn, fminf(fminf(nr.x, nr.y), fminf(nr.z, nr.w)));
        STEP(fv.x, nr.x); STEP(fv.y, nr.y);
        STEP(fv.z, nr.z); STEP(fv.w, nr.w);
    }

    {
        float4 p;
        UPK2(p.x, p.y, t01);
        UPK2(p.z, p.w, t23);
        sP[c][ql] = p;
    }
    if (ql == 0) spn[c] = pn;
    __syncthreads();

    // ---- Phase 2: fold exact init for this chunk (packed) ----
    float a0 = lam0, a1 = lam1, a2 = lam2, a3 = lam3;
#pragma unroll
    for (int s = 0; s < 5; ++s) { a0 *= a0; a1 *= a1; a2 *= a2; a3 *= a3; }
    uint64_t ap01, ap23;
    PK2(ap01, a0, a1);
    PK2(ap23, a2, a3);

    {
        const float4 cv = ((const float4*)carry)[q];
        PK2(t01, cv.x, cv.y);
        PK2(t23, cv.z, cv.w);
    }
    for (int j = 0; j < c; ++j) {
        const float4 P = sP[j][ql];
        const float  w = spn[j];
        uint64_t ww, c01, c23, P01, P23;
        PK2(ww, w, w);
        PK2(P01, P.x, P.y); PK2(P23, P.z, P.w);
        MUL2(c01, ap01, ww); MUL2(c23, ap23, ww);
        FMA2(t01, c01, t01, P01);
        FMA2(t23, c23, t23, P23);
    }

    // ---- Phase 3: re-run chunk from exact init, stream ys ----
    float* yb = out + BFL + t0 * BFL + q * 4;

#define EMIT(I)                                               \
    {   float4 o;                                             \
        UPK2(o.x, o.y, t01); UPK2(o.z, o.w, t23);             \
        __stcs((float4*)(yb + (I) * BFL), o);                 }

#pragma unroll
    for (int g = 0; g < CL / 4; ++g) {
        const float4 fv = *(const float4*)(fbase + 4 * g);
        const float4 nr = *(const float4*)(snr + t0 + 4 * g);
        STEP(fv.x, nr.x); EMIT(4 * g + 0);
        STEP(fv.y, nr.y); EMIT(4 * g + 1);
        STEP(fv.z, nr.z); EMIT(4 * g + 2);
        STEP(fv.w, nr.w); EMIT(4 * g + 3);
    }
#undef STEP
#undef EMIT

    if (c == CC - 1) {
        float4 o;
        UPK2(o.x, o.y, t01); UPK2(o.z, o.w, t23);
        ((float4*)out)[q] = o;   // final trace
    }
}

extern "C" void kernel_launch(void* const* d_in, const int* in_sizes, int n_in,
                              void* d_out, int out_size) {
    const float* features = (const float*)d_in[0];
    const int*   resets   = (const int*)d_in[1];
    const float* carry    = (const float*)d_in[2];
    const float* lambdas  = (const float*)d_in[3];
    float* out = (float*)d_out;

    trace_fused<<<QQ / QPB, NT>>>(features, resets, carry, lambdas, out);
}

// round 13
// speedup vs baseline: 1.3470x; 1.3470x over previous
#include <cuda_runtime.h>
#include <cstdint>

// TraceRNN: T=512, B=32, F=256, L=8
// out = [ final_trace : B*F*L ][ ys : T*B*F*L ]
// Fused chunked scan (16 chunks x 32 steps), quad-lambda threads, ONE kernel.
// R13: R10 structure exactly (256-thr blocks, smem snr, producer+flag),
//      with packed f32x2 arithmetic in STEP / phase-2.

#define TT  512
#define BB  32
#define FF  256
#define LL  8
#define BF  (BB * FF)        // 8192
#define BFL (BB * FF * LL)   // 65536
#define QQ  (BFL / 4)        // 16384 lambda-quads
#define CC  16
#define CL  32
#define QPB 16
#define NT  256
#define FSTR 516             // padded t-stride (words)
#define NPROD 16             // producer blocks

__device__ float g_snrT[BB * TT];   // [b][t] = reset ? 0 : 1
__device__ int   g_flag;            // monotonic producer counter

// ---- packed f32x2 helpers ----
#define PK2(d, lo, hi)  asm("mov.b64 %0, {%1,%2};" : "=l"(d) : "f"(lo), "f"(hi))
#define UPK2(lo, hi, s) asm("mov.b64 {%0,%1}, %2;" : "=f"(lo), "=f"(hi) : "l"(s))
#define MUL2(d, a, b)   asm("mul.rn.f32x2 %0, %1, %2;" : "=l"(d) : "l"(a), "l"(b))
#define SUB2(d, a, b)   asm("sub.rn.f32x2 %0, %1, %2;" : "=l"(d) : "l"(a), "l"(b))
#define FMA2(d, a, b, c) asm("fma.rn.f32x2 %0, %1, %2, %3;" : "=l"(d) : "l"(a), "l"(b), "l"(c))

__global__ __launch_bounds__(NT, 7) void trace_fused(
    const float* __restrict__ features,   // [T,B,F]
    const int*   __restrict__ resets,     // [T,B]
    const float* __restrict__ carry,      // [B,F,L]
    const float* __restrict__ lambdas,    // [L]
    float*       __restrict__ out)        // [BFL + T*BFL]
{
    __shared__ float  sfeatT[8 * FSTR];   // [fcol][t], ~16.5 KB
    __shared__ float  snr[TT];            // 2 KB
    __shared__ float4 sP[CC][QPB];        // 4 KB
    __shared__ float  spn[CC];

    const int tid  = threadIdx.x;
    const int ql   = tid & (QPB - 1);
    const int c    = tid >> 4;
    const int q    = blockIdx.x * QPB + ql;
    const int b    = q >> 9;
    const int col0 = (blockIdx.x * QPB) >> 1;  // first feature col of block
    const int fcol = ql >> 1;
    const int t0   = c * CL;

    // ---- stage features transposed: LDG.128 coalesced (R10 layout) ----
#pragma unroll
    for (int it = 0; it < 4; ++it) {
        const int idx = it * NT + tid;            // 0..1023
        const int t = idx >> 1, h = idx & 1;
        float4 v = *(const float4*)(features + t * BF + col0 + h * 4);
        sfeatT[(h * 4 + 0) * FSTR + t] = v.x;
        sfeatT[(h * 4 + 1) * FSTR + t] = v.y;
        sfeatT[(h * 4 + 2) * FSTR + t] = v.z;
        sfeatT[(h * 4 + 3) * FSTR + t] = v.w;
    }

    // ---- producer blocks: transpose a 32-t slice of resets -> g_snrT ----
    if (blockIdx.x < NPROD) {
        const int tbase = blockIdx.x * 32;
#pragma unroll
        for (int it = 0; it < 4; ++it) {
            const int idx = it * NT + tid;        // 0..1023
            const int tl = idx >> 5, bb = idx & 31;
            g_snrT[bb * TT + tbase + tl] =
                (resets[(tbase + tl) * BB + bb] != 0) ? 0.0f : 1.0f;
        }
        __threadfence();
        __syncthreads();
        if (tid == 0) atomicAdd(&g_flag, 1);
    }

    const int   l0   = (q & 1) * 4;
    const float lam0 = __ldg(&lambdas[l0 + 0]);
    const float lam1 = __ldg(&lambdas[l0 + 1]);
    const float lam2 = __ldg(&lambdas[l0 + 2]);
    const float lam3 = __ldg(&lambdas[l0 + 3]);
    uint64_t lam01, lam23;
    PK2(lam01, lam0, lam1);
    PK2(lam23, lam2, lam3);

    // ---- wait for producers, then load snr contiguously ----
    if (tid == 0) {
        while (*(volatile int*)&g_flag < NPROD) { }
        __threadfence();
    }
    __syncthreads();

#pragma unroll
    for (int it = 0; it < 2; ++it)
        snr[it * NT + tid] = g_snrT[b * TT + it * NT + tid];

    __syncthreads();

    const float* fbase = sfeatT + fcol * FSTR + t0;

    // ---- Phase 1: chunk summary with zero init ----
    uint64_t t01 = 0ull, t23 = 0ull;
    float pn = 1.0f;

#define STEP(FV, NR)                                          \
    {   const float _f = (FV), _n = (NR);                     \
        uint64_t _nn, _ff, _a01, _a23, _d01, _d23;            \
        PK2(_nn, _n, _n);  PK2(_ff, _f, _f);                  \
        MUL2(_a01, lam01, _nn); MUL2(_a23, lam23, _nn);       \
        SUB2(_d01, t01, _ff);   SUB2(_d23, t23, _ff);         \
        FMA2(t01, _a01, _d01, _ff);                           \
        FMA2(t23, _a23, _d23, _ff);                           }

#pragma unroll
    for (int g = 0; g < CL / 4; ++g) {
        const float4 fv = *(const float4*)(fbase + 4 * g);
        const float4 nr = *(const float4*)(snr + t0 + 4 * g);
        pn = fminf(pn, fminf(fminf(nr.x, nr.y), fminf(nr.z, nr.w)));
        STEP(fv.x, nr.x); STEP(fv.y, nr.y);
        STEP(fv.z, nr.z); STEP(fv.w, nr.w);
    }

    {
        float4 p;
        UPK2(p.x, p.y, t01);
        UPK2(p.z, p.w, t23);
        sP[c][ql] = p;
    }
    if (ql == 0) spn[c] = pn;
    __syncthreads();

    // ---- Phase 2: fold exact init for this chunk (packed) ----
    float a0 = lam0, a1 = lam1, a2 = lam2, a3 = lam3;
#pragma unroll
    for (int s = 0; s < 5; ++s) { a0 *= a0; a1 *= a1; a2 *= a2; a3 *= a3; }
    uint64_t ap01, ap23;
    PK2(ap01, a0, a1);
    PK2(ap23, a2, a3);

    {
        const float4 cv = ((const float4*)carry)[q];
        PK2(t01, cv.x, cv.y);
        PK2(t23, cv.z, cv.w);
    }
    for (int j = 0; j < c; ++j) {
        const float4 P = sP[j][ql];
        const float  w = spn[j];
        uint64_t ww, c01, c23, P01, P23;
        PK2(ww, w, w);
        PK2(P01, P.x, P.y); PK2(P23, P.z, P.w);
        MUL2(c01, ap01, ww); MUL2(c23, ap23, ww);
        FMA2(t01, c01, t01, P01);
        FMA2(t23, c23, t23, P23);
    }

    // ---- Phase 3: re-run chunk from exact init, stream ys ----
    float* yb = out + BFL + t0 * BFL + q * 4;

#define EMIT(I)                                               \
    {   float4 o;                                             \
        UPK2(o.x, o.y, t01); UPK2(o.z, o.w, t23);             \
        __stcs((float4*)(yb + (I) * BFL), o);                 }

#pragma unroll
    for (int g = 0; g < CL / 4; ++g) {
        const float4 fv = *(const float4*)(fbase + 4 * g);
        const float4 nr = *(const float4*)(snr + t0 + 4 * g);
        STEP(fv.x, nr.x); EMIT(4 * g + 0);
        STEP(fv.y, nr.y); EMIT(4 * g + 1);
        STEP(fv.z, nr.z); EMIT(4 * g + 2);
        STEP(fv.w, nr.w); EMIT(4 * g + 3);
    }
#undef STEP
#undef EMIT

    if (c == CC - 1) {
        float4 o;
        UPK2(o.x, o.y, t01); UPK2(o.z, o.w, t23);
        ((float4*)out)[q] = o;   // final trace
    }
}

extern "C" void kernel_launch(void* const* d_in, const int* in_sizes, int n_in,
                              void* d_out, int out_size) {
    const float* features = (const float*)d_in[0];
    const int*   resets   = (const int*)d_in[1];
    const float* carry    = (const float*)d_in[2];
    const float* lambdas  = (const float*)d_in[3];
    float* out = (float*)d_out;

    trace_fused<<<QQ / QPB, NT>>>(features, resets, carry, lambdas, out);
}